// round 16
// baseline (speedup 1.0000x reference)
#include <cuda_runtime.h>
#include <cuda_fp16.h>

#define T_LEN 4096
#define N_DIM 256
#define U_DIM 128
#define K_DIM 32
#define P_DIM 128
#define NK    8192   // N_DIM * K_DIM
#define CH_L  64     // chunk length
#define NCH   64     // number of chunks (T_LEN / CH_L)
#define G_T   8      // timesteps per k1 CTA

typedef unsigned long long u64;
typedef unsigned int u32;

// ---------------- device scratch (no runtime allocation allowed) ----------------
__device__ __half g_S_re[(size_t)T_LEN * NK];   // 67 MB: raw k1 output
__device__ __half g_S_im[(size_t)T_LEN * NK];   // 67 MB
// final states as pre-built fp16 B-fragments: per t, 4096 u64 = [32 s][32 lane][4 nt]
__device__ u64 g_Sf[(size_t)T_LEN * 4096];      // 134 MB
__device__ float g_send_re[NCH * NK];
__device__ float g_send_im[NCH * NK];
__device__ float g_carry_re[NCH * NK];
__device__ float g_carry_im[NCH * NK];
// x pre-converted to fp16 B-fragments: per t, 1024 u64 = [8 s][32 lane][4 nt]
__device__ u64 g_Xf16[(size_t)T_LEN * 1024];    // 33.5 MB
// k1 B weights as m16n8k16 A-fragments (fp16):
__device__ u32 g_Wfrag[2 * 16 * 8 * 128];
// k3 fused weight matrix W[p, j] (j = 640: Cre | -Cim | D) as fp16 A-fragments:
__device__ uint4 g_W3[8 * 40 * 32];

// ---------------- fp16 helpers ----------------
__device__ __forceinline__ u32 pack_h2(float lo, float hi) {
    __half2 h = __floats2half2_rn(lo, hi);
    return *(u32*)&h;
}
__device__ __forceinline__ float2 unpack_h2(u32 v) {
    __half2 h = *(__half2*)&v;
    return __half22float2(h);
}

// mma.sync m16n8k16 row.col f32.f16.f16.f32
__device__ __forceinline__ void mma16816h(float* c, const u32* a, const u32* b) {
    asm volatile(
        "mma.sync.aligned.m16n8k16.row.col.f32.f16.f16.f32 "
        "{%0,%1,%2,%3}, {%4,%5,%6,%7}, {%8,%9}, {%0,%1,%2,%3};"
        : "+f"(c[0]), "+f"(c[1]), "+f"(c[2]), "+f"(c[3])
        : "r"(a[0]), "r"(a[1]), "r"(a[2]), "r"(a[3]), "r"(b[0]), "r"(b[1]));
}

// ---------------- K0a: pack k1 B weights into A-fragment layout (fp16) ---------
__global__ __launch_bounds__(256) void k0_pack(
    const float* __restrict__ Bre, const float* __restrict__ Bim)
{
    int t = blockIdx.x * 256 + threadIdx.x;
    int r    = t & 3;
    int lane = (t >> 2) & 31;
    int s    = (t >> 7) & 7;
    int mt   = (t >> 10) & 15;
    int h    = t >> 14;
    int g = lane >> 2, c = lane & 3;
    int n = mt * 16 + g + ((r & 1) ? 8 : 0);
    int u = s * 16 + 2 * c + ((r & 2) ? 8 : 0);
    const float* W = h ? Bim : Bre;
    float f0 = W[n * U_DIM + u];
    float f1 = W[n * U_DIM + u + 1];
    g_Wfrag[(h * 16 + mt) * 1024 + s * 128 + lane * 4 + r] = pack_h2(f0, f1);
}

// ---------------- K0b: pack k3 fused weights [Cre | -Cim | D] (fp16) -----------
__global__ __launch_bounds__(256) void k0_pack3(
    const float* __restrict__ Cre, const float* __restrict__ Cim,
    const float* __restrict__ D)
{
    int t = blockIdx.x * 256 + threadIdx.x;
    if (t >= 10240) return;
    int lane = t & 31;
    int q = t >> 5;
    int s = q % 40;
    int mt = q / 40;
    int g = lane >> 2, c = lane & 3;
    u32 o[4];
#pragma unroll
    for (int r = 0; r < 4; r++) {
        int prow = mt * 16 + g + ((r & 1) ? 8 : 0);
        int jc = s * 16 + 2 * c + ((r & 2) ? 8 : 0);
        float f0, f1;
        if (s < 16) {
            f0 = Cre[prow * N_DIM + jc];
            f1 = Cre[prow * N_DIM + jc + 1];
        } else if (s < 32) {
            f0 = -Cim[prow * N_DIM + (jc - 256)];
            f1 = -Cim[prow * N_DIM + (jc - 256) + 1];
        } else {
            f0 = D[prow * U_DIM + (jc - 512)];
            f1 = D[prow * U_DIM + (jc - 512) + 1];
        }
        o[r] = pack_h2(f0, f1);
    }
    g_W3[t] = make_uint4(o[0], o[1], o[2], o[3]);
}

// ---------------- K0c: pre-convert x into fp16 B-fragments ---------------------
// NEW layout: dst index = s*128 + lane*4 + nt  (nt innermost -> LDG.128 reads)
__global__ __launch_bounds__(256) void k0_xfrag(const float* __restrict__ x)
{
    __shared__ float Xs[128 * 33];
    int tid = threadIdx.x;
    int t0 = blockIdx.x * 8;
    for (int tt = 0; tt < 8; tt++) {
        int t = t0 + tt;
        __syncthreads();
        const float* xp = x + (size_t)t * (U_DIM * K_DIM);
#pragma unroll
        for (int i = 0; i < 16; i++) {
            int e = tid + i * 256;
            Xs[(e >> 5) * 33 + (e & 31)] = xp[e];
        }
        __syncthreads();
        u64* dst = g_Xf16 + (size_t)t * 1024;
#pragma unroll
        for (int i = 0; i < 4; i++) {
            int slot = tid + i * 256;
            int sl = slot & 31;
            int nt = (slot >> 5) & 3;
            int s  = slot >> 7;
            int sg = sl >> 2, sc = sl & 3;
            int u0 = s * 16 + 2 * sc;
            int kc = nt * 8 + sg;
            float v0 = Xs[u0 * 33 + kc];
            float v1 = Xs[(u0 + 1) * 33 + kc];
            float v2 = Xs[(u0 + 8) * 33 + kc];
            float v3 = Xs[(u0 + 9) * 33 + kc];
            u32 b0 = pack_h2(v0, v1);
            u32 b1 = pack_h2(v2, v3);
            u64 pv;
            asm("mov.b64 %0, {%1, %2};" : "=l"(pv) : "r"(b0), "r"(b1));
            dst[s * 128 + sl * 4 + nt] = pv;
        }
    }
}

// ---------------- K1 (HMMA fp16): register-resident A, LDG.128 B loads ---------
__global__ __launch_bounds__(256, 2) void k1_mma()
{
    int tid = threadIdx.x;
    int w = tid >> 5, lane = tid & 31;
    int half = blockIdx.x;
    __half* dst = half ? g_S_im : g_S_re;
    int t0 = blockIdx.y * G_T;

    u32 a[2][8][4];
#pragma unroll
    for (int mtl = 0; mtl < 2; mtl++) {
        int mt = w * 2 + mtl;
#pragma unroll
        for (int s = 0; s < 8; s++) {
            uint4 v = ((const uint4*)(g_Wfrag + half * 16384 + mt * 1024 + s * 128))[lane];
            a[mtl][s][0] = v.x; a[mtl][s][1] = v.y; a[mtl][s][2] = v.z; a[mtl][s][3] = v.w;
        }
    }

    int g = lane >> 2, c = lane & 3;

    for (int tt = 0; tt < G_T; tt++) {
        int t = t0 + tt;
        const u64* xf = g_Xf16 + (size_t)t * 1024 + lane * 4;

        float acc[2][4][4];
#pragma unroll
        for (int mtl = 0; mtl < 2; mtl++)
#pragma unroll
            for (int nt = 0; nt < 4; nt++)
#pragma unroll
                for (int q = 0; q < 4; q++) acc[mtl][nt][q] = 0.f;

        u64 bv[4];
        {
            ulonglong2 q0 = *(const ulonglong2*)(xf);
            ulonglong2 q1 = *(const ulonglong2*)(xf + 2);
            bv[0] = q0.x; bv[1] = q0.y; bv[2] = q1.x; bv[3] = q1.y;
        }

#pragma unroll
        for (int s = 0; s < 8; s++) {
            u64 bvn[4];
            if (s < 7) {
                ulonglong2 q0 = *(const ulonglong2*)(xf + (s + 1) * 128);
                ulonglong2 q1 = *(const ulonglong2*)(xf + (s + 1) * 128 + 2);
                bvn[0] = q0.x; bvn[1] = q0.y; bvn[2] = q1.x; bvn[3] = q1.y;
            } else {
#pragma unroll
                for (int nt = 0; nt < 4; nt++) bvn[nt] = bv[nt];
            }
#pragma unroll
            for (int nt = 0; nt < 4; nt++) {
                u32 b[2];
                asm("mov.b64 {%0, %1}, %2;" : "=r"(b[0]), "=r"(b[1]) : "l"(bv[nt]));
#pragma unroll
                for (int mtl = 0; mtl < 2; mtl++)
                    mma16816h(acc[mtl][nt], a[mtl][s], b);
            }
#pragma unroll
            for (int nt = 0; nt < 4; nt++) bv[nt] = bvn[nt];
        }
        size_t tb = (size_t)t * NK;
#pragma unroll
        for (int mtl = 0; mtl < 2; mtl++) {
            int nrow = (w * 2 + mtl) * 16 + g;
#pragma unroll
            for (int nt = 0; nt < 4; nt++) {
                int kc = nt * 8 + 2 * c;
                *(u32*)&dst[tb + nrow * K_DIM + kc] = pack_h2(acc[mtl][nt][0], acc[mtl][nt][1]);
                *(u32*)&dst[tb + (nrow + 8) * K_DIM + kc] = pack_h2(acc[mtl][nt][2], acc[mtl][nt][3]);
            }
        }
    }
}

// ---------------- K2a: per-chunk sends only (read-only pass) -------------------
__global__ __launch_bounds__(256) void k2_send(
    const float* __restrict__ Are, const float* __restrict__ Aim)
{
    int c2 = (blockIdx.x * 256 + threadIdx.x) * 2;
    int chunk = blockIdx.y;
    float2 arv = *(const float2*)&Are[c2];
    float2 aiv = *(const float2*)&Aim[c2];
    float sr0 = 0.f, si0 = 0.f, sr1 = 0.f, si1 = 0.f;
    size_t base = (size_t)chunk * CH_L * NK + c2;
    for (int tg = 0; tg < CH_L; tg += 4) {
        u32 vr[4], vi[4];
#pragma unroll
        for (int j = 0; j < 4; j++) {
            vr[j] = *(const u32*)&g_S_re[base + (size_t)j * NK];
            vi[j] = *(const u32*)&g_S_im[base + (size_t)j * NK];
        }
#pragma unroll
        for (int j = 0; j < 4; j++) {
            float2 inr = unpack_h2(vr[j]);
            float2 ini = unpack_h2(vi[j]);
            float nr0 = fmaf(arv.x, sr0, fmaf(-aiv.x, si0, inr.x));
            float ni0 = fmaf(arv.x, si0, fmaf(aiv.x, sr0, ini.x));
            float nr1 = fmaf(arv.y, sr1, fmaf(-aiv.y, si1, inr.y));
            float ni1 = fmaf(arv.y, si1, fmaf(aiv.y, sr1, ini.y));
            sr0 = nr0; si0 = ni0; sr1 = nr1; si1 = ni1;
        }
        base += (size_t)4 * NK;
    }
    g_send_re[chunk * NK + c2] = sr0;
    g_send_re[chunk * NK + c2 + 1] = sr1;
    g_send_im[chunk * NK + c2] = si0;
    g_send_im[chunk * NK + c2 + 1] = si1;
}

// ---------------- K2b: cross-chunk carries (a^64 by squaring) ------------------
__global__ __launch_bounds__(256) void k2_carry(
    const float* __restrict__ Are, const float* __restrict__ Aim)
{
    int c = blockIdx.x * 256 + threadIdx.x;
    float qr = Are[c], qi = Aim[c];
#pragma unroll
    for (int j = 0; j < 6; j++) {
        float tr = qr * qr - qi * qi;
        qi = 2.f * qr * qi;
        qr = tr;
    }
    float a64r = qr, a64i = qi;
    float cr = 0.f, ci = 0.f;
    for (int ch = 0; ch < NCH; ch += 8) {
        float sr[8], si[8];
#pragma unroll
        for (int j = 0; j < 8; j++) {
            sr[j] = g_send_re[(ch + j) * NK + c];
            si[j] = g_send_im[(ch + j) * NK + c];
        }
#pragma unroll
        for (int j = 0; j < 8; j++) {
            g_carry_re[(ch + j) * NK + c] = cr;
            g_carry_im[(ch + j) * NK + c] = ci;
            float tmp = fmaf(a64r, cr, fmaf(-a64i, ci, sr[j]));
            ci = fmaf(a64r, ci, fmaf(a64i, cr, si[j]));
            cr = tmp;
        }
    }
}

// ---------------- K2c: scan with carry init; emit fp16 MMA B-fragments --------
// NEW g_Sf layout: offset = (sim*16+ng)*128 + lane*4 + ntl  (nt innermost)
__global__ __launch_bounds__(256) void k2_scan(
    const float* __restrict__ Are, const float* __restrict__ Aim)
{
    __shared__ float Tr[2][16 * 34];
    __shared__ float Ti[2][16 * 34];

    int tid = threadIdx.x;
    int ng = blockIdx.x;          // n-group (16 n rows)
    int chunk = blockIdx.y;
    int c2 = (ng * 256 + tid) * 2;
    float2 arv = *(const float2*)&Are[c2];
    float2 aiv = *(const float2*)&Aim[c2];
    float sr0 = g_carry_re[chunk * NK + c2];
    float sr1 = g_carry_re[chunk * NK + c2 + 1];
    float si0 = g_carry_im[chunk * NK + c2];
    float si1 = g_carry_im[chunk * NK + c2 + 1];

    int nloc = (c2 >> 5) & 15;
    int k0 = c2 & 31;
    int tso = nloc * 34 + k0;

    int lane = tid & 31;
    int ntl = (tid >> 5) & 3;
    int sim = tid >> 7;           // 0: re, 1: im
    int sg = lane >> 2, sc = lane & 3;
    int bk = ntl * 8 + sg;
    int r0 = 2 * sc, r2 = 2 * sc + 8;
    u64* sf_base = g_Sf + (size_t)(chunk * CH_L) * 4096
                 + (sim * 16 + ng) * 128 + lane * 4 + ntl;

    size_t base = (size_t)chunk * CH_L * NK + c2;
    u32 pre_r = *(const u32*)&g_S_re[base];
    u32 pre_i = *(const u32*)&g_S_im[base];

    for (int tl = 0; tl < CH_L; tl++) {
        int buf = tl & 1;
        u32 vr = pre_r, vi = pre_i;
        if (tl < CH_L - 1) {
            pre_r = *(const u32*)&g_S_re[base + NK];
            pre_i = *(const u32*)&g_S_im[base + NK];
        }
        float2 inr = unpack_h2(vr);
        float2 ini = unpack_h2(vi);
        float nr0 = fmaf(arv.x, sr0, fmaf(-aiv.x, si0, inr.x));
        float ni0 = fmaf(arv.x, si0, fmaf(aiv.x, sr0, ini.x));
        float nr1 = fmaf(arv.y, sr1, fmaf(-aiv.y, si1, inr.y));
        float ni1 = fmaf(arv.y, si1, fmaf(aiv.y, sr1, ini.y));
        sr0 = nr0; si0 = ni0; sr1 = nr1; si1 = ni1;
        Tr[buf][tso] = sr0; Tr[buf][tso + 1] = sr1;
        Ti[buf][tso] = si0; Ti[buf][tso + 1] = si1;
        __syncthreads();
        const float* T = sim ? Ti[buf] : Tr[buf];
        float v0 = T[r0 * 34 + bk];
        float v1 = T[(r0 + 1) * 34 + bk];
        float v2 = T[r2 * 34 + bk];
        float v3 = T[(r2 + 1) * 34 + bk];
        u32 b0 = pack_h2(v0, v1);
        u32 b1 = pack_h2(v2, v3);
        u64 pv;
        asm("mov.b64 %0, {%1, %2};" : "=l"(pv) : "r"(b0), "r"(b1));
        sf_base[(size_t)tl * 4096] = pv;
        base += NK;
    }
}

// ---------------- K3 (HMMA fp16): pure LDG.128+MMA, no smem, no syncs ----------
__global__ __launch_bounds__(256, 3) void k3_mma(float* __restrict__ out)
{
    int tid = threadIdx.x;
    int w = tid >> 5, lane = tid & 31;
    int t0 = blockIdx.x * 2;

    float acc[8][4];
#pragma unroll
    for (int nt = 0; nt < 8; nt++)
#pragma unroll
        for (int qq = 0; qq < 4; qq++) acc[nt][qq] = 0.f;

    const u64* sf0 = g_Sf + (size_t)t0 * 4096 + lane * 4;

#pragma unroll 1
    for (int s = 0; s < 32; s++) {
        const uint4* wp = g_W3 + (w * 40 + s) * 32;
        uint4 v = wp[lane];
        u32 a[4] = {v.x, v.y, v.z, v.w};
        u64 bv[8];
        {
            const u64* p = sf0 + s * 128;
            ulonglong2 q0 = *(const ulonglong2*)(p);
            ulonglong2 q1 = *(const ulonglong2*)(p + 2);
            ulonglong2 q2 = *(const ulonglong2*)(p + 4096);
            ulonglong2 q3 = *(const ulonglong2*)(p + 4096 + 2);
            bv[0] = q0.x; bv[1] = q0.y; bv[2] = q1.x; bv[3] = q1.y;
            bv[4] = q2.x; bv[5] = q2.y; bv[6] = q3.x; bv[7] = q3.y;
        }
#pragma unroll
        for (int nt = 0; nt < 8; nt++) {
            u32 bb[2];
            asm("mov.b64 {%0, %1}, %2;" : "=r"(bb[0]), "=r"(bb[1]) : "l"(bv[nt]));
            mma16816h(acc[nt], a, bb);
        }
    }

    // ---- D branch: x fragments direct from g_Xf16 (new layout)
    const u64* xf0 = g_Xf16 + (size_t)t0 * 1024 + lane * 4;
#pragma unroll 1
    for (int si = 0; si < 8; si++) {
        const uint4* wp = g_W3 + (w * 40 + 32 + si) * 32;
        uint4 v = wp[lane];
        u32 a[4] = {v.x, v.y, v.z, v.w};
        u64 bv[8];
        {
            const u64* p = xf0 + si * 128;
            ulonglong2 q0 = *(const ulonglong2*)(p);
            ulonglong2 q1 = *(const ulonglong2*)(p + 2);
            ulonglong2 q2 = *(const ulonglong2*)(p + 1024);
            ulonglong2 q3 = *(const ulonglong2*)(p + 1024 + 2);
            bv[0] = q0.x; bv[1] = q0.y; bv[2] = q1.x; bv[3] = q1.y;
            bv[4] = q2.x; bv[5] = q2.y; bv[6] = q3.x; bv[7] = q3.y;
        }
#pragma unroll
        for (int nt = 0; nt < 8; nt++) {
            u32 bb[2];
            asm("mov.b64 {%0, %1}, %2;" : "=r"(bb[0]), "=r"(bb[1]) : "l"(bv[nt]));
            mma16816h(acc[nt], a, bb);
        }
    }

    // ---- epilogue
    int g_ = lane >> 2, c_ = lane & 3;
#pragma unroll
    for (int nt = 0; nt < 8; nt++) {
        int col = nt * 8 + 2 * c_;
        int t = t0 + (col >> 5);
        int k = col & 31;
        int p = w * 16 + g_;
        *(float2*)(out + (size_t)t * (P_DIM * K_DIM) + p * K_DIM + k) =
            make_float2(acc[nt][0], acc[nt][1]);
        *(float2*)(out + (size_t)t * (P_DIM * K_DIM) + (p + 8) * K_DIM + k) =
            make_float2(acc[nt][2], acc[nt][3]);
    }
}

// ---------------- launch ----------------
extern "C" void kernel_launch(void* const* d_in, const int* in_sizes, int n_in,
                              void* d_out, int out_size)
{
    const float* x   = (const float*)d_in[0];
    const float* Are = (const float*)d_in[1];
    const float* Aim = (const float*)d_in[2];
    const float* Bre = (const float*)d_in[3];
    const float* Bim = (const float*)d_in[4];
    const float* Cre = (const float*)d_in[5];
    const float* Cim = (const float*)d_in[6];
    const float* D   = (const float*)d_in[7];
    float* out = (float*)d_out;

    k0_pack<<<128, 256>>>(Bre, Bim);
    k0_pack3<<<40, 256>>>(Cre, Cim, D);
    k0_xfrag<<<512, 256>>>(x);

    k1_mma<<<dim3(2, T_LEN / G_T), 256>>>();

    dim3 g2(NK / 512, NCH);
    k2_send<<<g2, 256>>>(Are, Aim);
    k2_carry<<<NK / 256, 256>>>(Are, Aim);
    k2_scan<<<g2, 256>>>(Are, Aim);

    k3_mma<<<T_LEN / 2, 256>>>(out);
}

// round 17
// speedup vs baseline: 1.1433x; 1.1433x over previous
#include <cuda_runtime.h>
#include <cuda_fp16.h>

#define T_LEN 4096
#define N_DIM 256
#define U_DIM 128
#define K_DIM 32
#define P_DIM 128
#define NK    8192   // N_DIM * K_DIM
#define CH_L  64     // chunk length
#define NCH   64     // number of chunks (T_LEN / CH_L)
#define G_T   8      // timesteps per k1 CTA

typedef unsigned long long u64;
typedef unsigned int u32;

// ---------------- device scratch (no runtime allocation allowed) ----------------
__device__ __half g_S_re[(size_t)T_LEN * NK];   // 67 MB: raw k1 output
__device__ __half g_S_im[(size_t)T_LEN * NK];   // 67 MB
// final states as pre-built fp16 B-fragments: per t, 4096 u64 = [32 s][4 nt][32 lane]
__device__ u64 g_Sf[(size_t)T_LEN * 4096];      // 134 MB
__device__ float g_send_re[NCH * NK];
__device__ float g_send_im[NCH * NK];
__device__ float g_carry_re[NCH * NK];
__device__ float g_carry_im[NCH * NK];
// x pre-converted to fp16 B-fragments: per t, 1024 u64 = [8 s][4 nt][32 lane]
__device__ u64 g_Xf16[(size_t)T_LEN * 1024];    // 33.5 MB
// k1 B weights as m16n8k16 A-fragments (fp16):
__device__ u32 g_Wfrag[2 * 16 * 8 * 128];
// k3 fused weight matrix W[p, j] (j = 640: Cre | -Cim | D) as fp16 A-fragments:
__device__ uint4 g_W3[8 * 40 * 32];

// ---------------- fp16 helpers ----------------
__device__ __forceinline__ u32 pack_h2(float lo, float hi) {
    __half2 h = __floats2half2_rn(lo, hi);
    return *(u32*)&h;
}
__device__ __forceinline__ float2 unpack_h2(u32 v) {
    __half2 h = *(__half2*)&v;
    return __half22float2(h);
}

// mma.sync m16n8k16 row.col f32.f16.f16.f32
__device__ __forceinline__ void mma16816h(float* c, const u32* a, const u32* b) {
    asm volatile(
        "mma.sync.aligned.m16n8k16.row.col.f32.f16.f16.f32 "
        "{%0,%1,%2,%3}, {%4,%5,%6,%7}, {%8,%9}, {%0,%1,%2,%3};"
        : "+f"(c[0]), "+f"(c[1]), "+f"(c[2]), "+f"(c[3])
        : "r"(a[0]), "r"(a[1]), "r"(a[2]), "r"(a[3]), "r"(b[0]), "r"(b[1]));
}

// ---------------- K0a: pack k1 B weights into A-fragment layout (fp16) ---------
__global__ __launch_bounds__(256) void k0_pack(
    const float* __restrict__ Bre, const float* __restrict__ Bim)
{
    int t = blockIdx.x * 256 + threadIdx.x;
    int r    = t & 3;
    int lane = (t >> 2) & 31;
    int s    = (t >> 7) & 7;
    int mt   = (t >> 10) & 15;
    int h    = t >> 14;
    int g = lane >> 2, c = lane & 3;
    int n = mt * 16 + g + ((r & 1) ? 8 : 0);
    int u = s * 16 + 2 * c + ((r & 2) ? 8 : 0);
    const float* W = h ? Bim : Bre;
    float f0 = W[n * U_DIM + u];
    float f1 = W[n * U_DIM + u + 1];
    g_Wfrag[(h * 16 + mt) * 1024 + s * 128 + lane * 4 + r] = pack_h2(f0, f1);
}

// ---------------- K0b: pack k3 fused weights [Cre | -Cim | D] (fp16) -----------
__global__ __launch_bounds__(256) void k0_pack3(
    const float* __restrict__ Cre, const float* __restrict__ Cim,
    const float* __restrict__ D)
{
    int t = blockIdx.x * 256 + threadIdx.x;
    if (t >= 10240) return;
    int lane = t & 31;
    int q = t >> 5;
    int s = q % 40;
    int mt = q / 40;
    int g = lane >> 2, c = lane & 3;
    u32 o[4];
#pragma unroll
    for (int r = 0; r < 4; r++) {
        int prow = mt * 16 + g + ((r & 1) ? 8 : 0);
        int jc = s * 16 + 2 * c + ((r & 2) ? 8 : 0);
        float f0, f1;
        if (s < 16) {
            f0 = Cre[prow * N_DIM + jc];
            f1 = Cre[prow * N_DIM + jc + 1];
        } else if (s < 32) {
            f0 = -Cim[prow * N_DIM + (jc - 256)];
            f1 = -Cim[prow * N_DIM + (jc - 256) + 1];
        } else {
            f0 = D[prow * U_DIM + (jc - 512)];
            f1 = D[prow * U_DIM + (jc - 512) + 1];
        }
        o[r] = pack_h2(f0, f1);
    }
    g_W3[t] = make_uint4(o[0], o[1], o[2], o[3]);
}

// ---------------- K0c: pre-convert x into fp16 B-fragments ---------------------
__global__ __launch_bounds__(256) void k0_xfrag(const float* __restrict__ x)
{
    __shared__ float Xs[128 * 33];
    int tid = threadIdx.x;
    int t0 = blockIdx.x * 8;
    for (int tt = 0; tt < 8; tt++) {
        int t = t0 + tt;
        __syncthreads();
        const float* xp = x + (size_t)t * (U_DIM * K_DIM);
#pragma unroll
        for (int i = 0; i < 16; i++) {
            int e = tid + i * 256;
            Xs[(e >> 5) * 33 + (e & 31)] = xp[e];
        }
        __syncthreads();
        u64* dst = g_Xf16 + (size_t)t * 1024;
#pragma unroll
        for (int i = 0; i < 4; i++) {
            int slot = tid + i * 256;
            int sl = slot & 31;
            int nt = (slot >> 5) & 3;
            int s  = slot >> 7;
            int sg = sl >> 2, sc = sl & 3;
            int u0 = s * 16 + 2 * sc;
            int kc = nt * 8 + sg;
            float v0 = Xs[u0 * 33 + kc];
            float v1 = Xs[(u0 + 1) * 33 + kc];
            float v2 = Xs[(u0 + 8) * 33 + kc];
            float v3 = Xs[(u0 + 9) * 33 + kc];
            u32 b0 = pack_h2(v0, v1);
            u32 b1 = pack_h2(v2, v3);
            u64 pv;
            asm("mov.b64 %0, {%1, %2};" : "=l"(pv) : "r"(b0), "r"(b1));
            dst[slot] = pv;
        }
    }
}

// ---------------- K1 (HMMA fp16): register-resident A, pure LDG+MMA loop -------
// EXACT R12 configuration (best measured: 75 us).
__global__ __launch_bounds__(256, 2) void k1_mma()
{
    int tid = threadIdx.x;
    int w = tid >> 5, lane = tid & 31;
    int half = blockIdx.x;
    __half* dst = half ? g_S_im : g_S_re;
    int t0 = blockIdx.y * G_T;

    u32 a[2][8][4];
#pragma unroll
    for (int mtl = 0; mtl < 2; mtl++) {
        int mt = w * 2 + mtl;
#pragma unroll
        for (int s = 0; s < 8; s++) {
            uint4 v = ((const uint4*)(g_Wfrag + half * 16384 + mt * 1024 + s * 128))[lane];
            a[mtl][s][0] = v.x; a[mtl][s][1] = v.y; a[mtl][s][2] = v.z; a[mtl][s][3] = v.w;
        }
    }

    int g = lane >> 2, c = lane & 3;

    for (int tt = 0; tt < G_T; tt++) {
        int t = t0 + tt;
        const u64* xf = g_Xf16 + (size_t)t * 1024;

        float acc[2][4][4];
#pragma unroll
        for (int mtl = 0; mtl < 2; mtl++)
#pragma unroll
            for (int nt = 0; nt < 4; nt++)
#pragma unroll
                for (int q = 0; q < 4; q++) acc[mtl][nt][q] = 0.f;

        u64 bv[4];
#pragma unroll
        for (int nt = 0; nt < 4; nt++) bv[nt] = xf[nt * 32 + lane];

#pragma unroll
        for (int s = 0; s < 8; s++) {
            u64 bvn[4];
#pragma unroll
            for (int nt = 0; nt < 4; nt++)
                bvn[nt] = (s < 7) ? xf[((s + 1) * 4 + nt) * 32 + lane] : bv[nt];
#pragma unroll
            for (int nt = 0; nt < 4; nt++) {
                u32 b[2];
                asm("mov.b64 {%0, %1}, %2;" : "=r"(b[0]), "=r"(b[1]) : "l"(bv[nt]));
#pragma unroll
                for (int mtl = 0; mtl < 2; mtl++)
                    mma16816h(acc[mtl][nt], a[mtl][s], b);
            }
#pragma unroll
            for (int nt = 0; nt < 4; nt++) bv[nt] = bvn[nt];
        }
        size_t tb = (size_t)t * NK;
#pragma unroll
        for (int mtl = 0; mtl < 2; mtl++) {
            int nrow = (w * 2 + mtl) * 16 + g;
#pragma unroll
            for (int nt = 0; nt < 4; nt++) {
                int kc = nt * 8 + 2 * c;
                *(u32*)&dst[tb + nrow * K_DIM + kc] = pack_h2(acc[mtl][nt][0], acc[mtl][nt][1]);
                *(u32*)&dst[tb + (nrow + 8) * K_DIM + kc] = pack_h2(acc[mtl][nt][2], acc[mtl][nt][3]);
            }
        }
    }
}

// ---------------- K2a: per-chunk sends only (read-only pass) -------------------
__global__ __launch_bounds__(256) void k2_send(
    const float* __restrict__ Are, const float* __restrict__ Aim)
{
    int c2 = (blockIdx.x * 256 + threadIdx.x) * 2;
    int chunk = blockIdx.y;
    float2 arv = *(const float2*)&Are[c2];
    float2 aiv = *(const float2*)&Aim[c2];
    float sr0 = 0.f, si0 = 0.f, sr1 = 0.f, si1 = 0.f;
    size_t base = (size_t)chunk * CH_L * NK + c2;
    for (int tg = 0; tg < CH_L; tg += 4) {
        u32 vr[4], vi[4];
#pragma unroll
        for (int j = 0; j < 4; j++) {
            vr[j] = *(const u32*)&g_S_re[base + (size_t)j * NK];
            vi[j] = *(const u32*)&g_S_im[base + (size_t)j * NK];
        }
#pragma unroll
        for (int j = 0; j < 4; j++) {
            float2 inr = unpack_h2(vr[j]);
            float2 ini = unpack_h2(vi[j]);
            float nr0 = fmaf(arv.x, sr0, fmaf(-aiv.x, si0, inr.x));
            float ni0 = fmaf(arv.x, si0, fmaf(aiv.x, sr0, ini.x));
            float nr1 = fmaf(arv.y, sr1, fmaf(-aiv.y, si1, inr.y));
            float ni1 = fmaf(arv.y, si1, fmaf(aiv.y, sr1, ini.y));
            sr0 = nr0; si0 = ni0; sr1 = nr1; si1 = ni1;
        }
        base += (size_t)4 * NK;
    }
    g_send_re[chunk * NK + c2] = sr0;
    g_send_re[chunk * NK + c2 + 1] = sr1;
    g_send_im[chunk * NK + c2] = si0;
    g_send_im[chunk * NK + c2 + 1] = si1;
}

// ---------------- K2b: cross-chunk carries (a^64 by squaring) ------------------
__global__ __launch_bounds__(256) void k2_carry(
    const float* __restrict__ Are, const float* __restrict__ Aim)
{
    int c = blockIdx.x * 256 + threadIdx.x;
    float qr = Are[c], qi = Aim[c];
#pragma unroll
    for (int j = 0; j < 6; j++) {
        float tr = qr * qr - qi * qi;
        qi = 2.f * qr * qi;
        qr = tr;
    }
    float a64r = qr, a64i = qi;
    float cr = 0.f, ci = 0.f;
    for (int ch = 0; ch < NCH; ch += 8) {
        float sr[8], si[8];
#pragma unroll
        for (int j = 0; j < 8; j++) {
            sr[j] = g_send_re[(ch + j) * NK + c];
            si[j] = g_send_im[(ch + j) * NK + c];
        }
#pragma unroll
        for (int j = 0; j < 8; j++) {
            g_carry_re[(ch + j) * NK + c] = cr;
            g_carry_im[(ch + j) * NK + c] = ci;
            float tmp = fmaf(a64r, cr, fmaf(-a64i, ci, sr[j]));
            ci = fmaf(a64r, ci, fmaf(a64i, cr, si[j]));
            cr = tmp;
        }
    }
}

// ---------------- K2c: scan with carry init; emit fp16 MMA B-fragments --------
// R12 layout: offset = (sim*16+ng)*128 + ntl*32 + lane
__global__ __launch_bounds__(256) void k2_scan(
    const float* __restrict__ Are, const float* __restrict__ Aim)
{
    __shared__ float Tr[2][16 * 34];
    __shared__ float Ti[2][16 * 34];

    int tid = threadIdx.x;
    int ng = blockIdx.x;          // n-group (16 n rows)
    int chunk = blockIdx.y;
    int c2 = (ng * 256 + tid) * 2;
    float2 arv = *(const float2*)&Are[c2];
    float2 aiv = *(const float2*)&Aim[c2];
    float sr0 = g_carry_re[chunk * NK + c2];
    float sr1 = g_carry_re[chunk * NK + c2 + 1];
    float si0 = g_carry_im[chunk * NK + c2];
    float si1 = g_carry_im[chunk * NK + c2 + 1];

    int nloc = (c2 >> 5) & 15;
    int k0 = c2 & 31;
    int tso = nloc * 34 + k0;

    int lane = tid & 31;
    int ntl = (tid >> 5) & 3;
    int sim = tid >> 7;           // 0: re, 1: im
    int sg = lane >> 2, sc = lane & 3;
    int bk = ntl * 8 + sg;
    int r0 = 2 * sc, r2 = 2 * sc + 8;
    u64* sf_base = g_Sf + (size_t)(chunk * CH_L) * 4096
                 + (sim * 16 + ng) * 128 + ntl * 32 + lane;

    size_t base = (size_t)chunk * CH_L * NK + c2;
    u32 pre_r = *(const u32*)&g_S_re[base];
    u32 pre_i = *(const u32*)&g_S_im[base];

    for (int tl = 0; tl < CH_L; tl++) {
        int buf = tl & 1;
        u32 vr = pre_r, vi = pre_i;
        if (tl < CH_L - 1) {
            pre_r = *(const u32*)&g_S_re[base + NK];
            pre_i = *(const u32*)&g_S_im[base + NK];
        }
        float2 inr = unpack_h2(vr);
        float2 ini = unpack_h2(vi);
        float nr0 = fmaf(arv.x, sr0, fmaf(-aiv.x, si0, inr.x));
        float ni0 = fmaf(arv.x, si0, fmaf(aiv.x, sr0, ini.x));
        float nr1 = fmaf(arv.y, sr1, fmaf(-aiv.y, si1, inr.y));
        float ni1 = fmaf(arv.y, si1, fmaf(aiv.y, sr1, ini.y));
        sr0 = nr0; si0 = ni0; sr1 = nr1; si1 = ni1;
        Tr[buf][tso] = sr0; Tr[buf][tso + 1] = sr1;
        Ti[buf][tso] = si0; Ti[buf][tso + 1] = si1;
        __syncthreads();
        const float* T = sim ? Ti[buf] : Tr[buf];
        float v0 = T[r0 * 34 + bk];
        float v1 = T[(r0 + 1) * 34 + bk];
        float v2 = T[r2 * 34 + bk];
        float v3 = T[(r2 + 1) * 34 + bk];
        u32 b0 = pack_h2(v0, v1);
        u32 b1 = pack_h2(v2, v3);
        u64 pv;
        asm("mov.b64 %0, {%1, %2};" : "=l"(pv) : "r"(b0), "r"(b1));
        sf_base[(size_t)tl * 4096] = pv;
        base += NK;
    }
}

// ---------------- K3 (HMMA fp16): 4t/CTA, 2 warp-groups, 2 m-tiles per warp ----
// warp group wg = w>>2 handles t-pair (t0+2wg, t0+2wg+1); warp wl = w&3 owns
// m-tiles {2wl, 2wl+1}. Per s: 16 MMAs per (8 B-loads + 2 W-loads).
__global__ __launch_bounds__(256, 2) void k3_mma(float* __restrict__ out)
{
    int tid = threadIdx.x;
    int w = tid >> 5, lane = tid & 31;
    int wg = w >> 2;
    int wl = w & 3;
    int t0 = blockIdx.x * 4;
    int tp = t0 + wg * 2;

    float acc[2][8][4];   // [mtl][tt2*4+ntl][q]
#pragma unroll
    for (int mtl = 0; mtl < 2; mtl++)
#pragma unroll
        for (int nt = 0; nt < 8; nt++)
#pragma unroll
            for (int qq = 0; qq < 4; qq++) acc[mtl][nt][qq] = 0.f;

    const u64* sf0 = g_Sf + (size_t)tp * 4096 + lane;

#pragma unroll 1
    for (int s = 0; s < 32; s++) {
        u32 a[2][4];
#pragma unroll
        for (int mtl = 0; mtl < 2; mtl++) {
            uint4 v = ((const uint4*)(g_W3 + ((wl * 2 + mtl) * 40 + s) * 32))[lane];
            a[mtl][0] = v.x; a[mtl][1] = v.y; a[mtl][2] = v.z; a[mtl][3] = v.w;
        }
        u64 bv[8];
#pragma unroll
        for (int tt2 = 0; tt2 < 2; tt2++)
#pragma unroll
            for (int ntl = 0; ntl < 4; ntl++)
                bv[tt2 * 4 + ntl] = sf0[(size_t)tt2 * 4096 + s * 128 + ntl * 32];
#pragma unroll
        for (int nt = 0; nt < 8; nt++) {
            u32 bb[2];
            asm("mov.b64 {%0, %1}, %2;" : "=r"(bb[0]), "=r"(bb[1]) : "l"(bv[nt]));
#pragma unroll
            for (int mtl = 0; mtl < 2; mtl++)
                mma16816h(acc[mtl][nt], a[mtl], bb);
        }
    }

    // ---- D branch: x fragments from g_Xf16
    const u64* xf0 = g_Xf16 + (size_t)tp * 1024 + lane;
#pragma unroll 1
    for (int si = 0; si < 8; si++) {
        u32 a[2][4];
#pragma unroll
        for (int mtl = 0; mtl < 2; mtl++) {
            uint4 v = ((const uint4*)(g_W3 + ((wl * 2 + mtl) * 40 + 32 + si) * 32))[lane];
            a[mtl][0] = v.x; a[mtl][1] = v.y; a[mtl][2] = v.z; a[mtl][3] = v.w;
        }
        u64 bv[8];
#pragma unroll
        for (int tt2 = 0; tt2 < 2; tt2++)
#pragma unroll
            for (int ntl = 0; ntl < 4; ntl++)
                bv[tt2 * 4 + ntl] = xf0[(size_t)tt2 * 1024 + si * 128 + ntl * 32];
#pragma unroll
        for (int nt = 0; nt < 8; nt++) {
            u32 bb[2];
            asm("mov.b64 {%0, %1}, %2;" : "=r"(bb[0]), "=r"(bb[1]) : "l"(bv[nt]));
#pragma unroll
            for (int mtl = 0; mtl < 2; mtl++)
                mma16816h(acc[mtl][nt], a[mtl], bb);
        }
    }

    // ---- epilogue
    int g_ = lane >> 2, c_ = lane & 3;
#pragma unroll
    for (int mtl = 0; mtl < 2; mtl++) {
        int p = (wl * 2 + mtl) * 16 + g_;
#pragma unroll
        for (int nt = 0; nt < 8; nt++) {
            int tt2 = nt >> 2, ntl = nt & 3;
            int t = tp + tt2;
            int k = ntl * 8 + 2 * c_;
            *(float2*)(out + (size_t)t * (P_DIM * K_DIM) + p * K_DIM + k) =
                make_float2(acc[mtl][nt][0], acc[mtl][nt][1]);
            *(float2*)(out + (size_t)t * (P_DIM * K_DIM) + (p + 8) * K_DIM + k) =
                make_float2(acc[mtl][nt][2], acc[mtl][nt][3]);
        }
    }
}

// ---------------- launch ----------------
extern "C" void kernel_launch(void* const* d_in, const int* in_sizes, int n_in,
                              void* d_out, int out_size)
{
    const float* x   = (const float*)d_in[0];
    const float* Are = (const float*)d_in[1];
    const float* Aim = (const float*)d_in[2];
    const float* Bre = (const float*)d_in[3];
    const float* Bim = (const float*)d_in[4];
    const float* Cre = (const float*)d_in[5];
    const float* Cim = (const float*)d_in[6];
    const float* D   = (const float*)d_in[7];
    float* out = (float*)d_out;

    k0_pack<<<128, 256>>>(Bre, Bim);
    k0_pack3<<<40, 256>>>(Cre, Cim, D);
    k0_xfrag<<<512, 256>>>(x);

    k1_mma<<<dim3(2, T_LEN / G_T), 256>>>();

    dim3 g2(NK / 512, NCH);
    k2_send<<<g2, 256>>>(Are, Aim);
    k2_carry<<<NK / 256, 256>>>(Are, Aim);
    k2_scan<<<g2, 256>>>(Are, Aim);

    k3_mma<<<T_LEN / 4, 256>>>(out);
}